// round 6
// baseline (speedup 1.0000x reference)
#include <cuda_runtime.h>
#include <math.h>

#define HID   128
#define NG    20
#define EF    4
#define ZDIM  280      // 2*HID + NG + EF
#define NZDIM 256      // 2*HID
#define TE    32       // edges (or nodes) per CTA tile
#define NTHR  256
#define MAXN  50000

// Scratch (static device arrays — no runtime allocation).
__device__ float g_mi[(size_t)MAXN * HID];
__device__ float g_dx[(size_t)MAXN * 3];

__device__ __forceinline__ float siluf(float v) {
    return v * (1.0f / (1.0f + __expf(-v)));
}

// Robust edge-index fetch: buffer may be int32 or little-endian int64.
// is64 -> payload at even int32 positions.
__device__ __forceinline__ int load_idx(const int* __restrict__ ei32,
                                        long long pos, int is64, int N) {
    int v = is64 ? ei32[2 * pos] : ei32[pos];
    // clamp defensively: wrong value -> rel_err, never an illegal access
    v = v < 0 ? 0 : v;
    return v >= N ? N - 1 : v;
}

// ----------------------------------------------------------------------------
// Register-blocked tile GEMM core: C[32][128] = A[32][K] @ W[K][128] + bias
// lane -> 4 consecutive output features (f0 = lane*4), warp -> 4 rows.
// A reads are warp-uniform smem broadcasts; W reads are float4-coalesced.
// ----------------------------------------------------------------------------
template<int K, int AS>
__device__ __forceinline__ void gemm_core(const float* __restrict__ sA,
                                          const float* __restrict__ W,
                                          const float* __restrict__ bias,
                                          float (&acc)[4][4], int e0, int f0)
{
    float4 bv = *(const float4*)&bias[f0];
    #pragma unroll
    for (int i = 0; i < 4; i++) {
        acc[i][0] = bv.x; acc[i][1] = bv.y; acc[i][2] = bv.z; acc[i][3] = bv.w;
    }
    #pragma unroll 2
    for (int k = 0; k < K; k += 4) {
        float4 wq[4];
        #pragma unroll
        for (int kk = 0; kk < 4; kk++)
            wq[kk] = *(const float4*)&W[(k + kk) * HID + f0];
        const float* wv = (const float*)wq;   // wv[kk*4 + j]
        #pragma unroll
        for (int i = 0; i < 4; i++) {
            float4 aq = *(const float4*)&sA[(e0 + i) * AS + k];  // broadcast
            float av[4] = {aq.x, aq.y, aq.z, aq.w};
            #pragma unroll
            for (int kk = 0; kk < 4; kk++)
                #pragma unroll
                for (int j = 0; j < 4; j++)
                    acc[i][j] = fmaf(av[kk], wv[kk * 4 + j], acc[i][j]);
        }
    }
}

__device__ __forceinline__ void store_silu(float (&acc)[4][4],
                                           float* __restrict__ sC, int e0, int f0)
{
    #pragma unroll
    for (int i = 0; i < 4; i++) {
        float4 o;
        o.x = siluf(acc[i][0]); o.y = siluf(acc[i][1]);
        o.z = siluf(acc[i][2]); o.w = siluf(acc[i][3]);
        *(float4*)&sC[(e0 + i) * HID + f0] = o;
    }
}

// ----------------------------------------------------------------------------
__global__ void zero_kernel()
{
    int i = blockIdx.x * blockDim.x + threadIdx.x;
    if (i < MAXN * HID) g_mi[i] = 0.0f;
    if (i < MAXN * 3)   g_dx[i] = 0.0f;
}

// ----------------------------------------------------------------------------
// Edge kernel: fused z -> silu -> silu -> {eij, silu -> xg} -> atomic scatter.
// ----------------------------------------------------------------------------
__global__ void __launch_bounds__(NTHR, 2)
edge_kernel(const float* __restrict__ h, const float* __restrict__ x,
            const int* __restrict__ ei32, const float* __restrict__ eattr,
            const float* __restrict__ We1, const float* __restrict__ be1,
            const float* __restrict__ We2, const float* __restrict__ be2,
            const float* __restrict__ Winf, const float* __restrict__ binf,
            const float* __restrict__ Wx1, const float* __restrict__ bx1,
            const float* __restrict__ Wx2, int E, int N)
{
    extern __shared__ float smem[];
    float* Z = smem;                 // [TE][ZDIM]
    float* U = smem + TE * ZDIM;     // [TE][HID]
    float* M = smem;                 // alias Z (dead after GEMM1)
    float* V = U;                    // alias U (dead after GEMM2)

    __shared__ float sRel[TE][3];
    __shared__ float sD[TE];
    __shared__ float sE[TE];
    __shared__ float sXg[TE];
    __shared__ int   sDst[TE];

    const int tid  = threadIdx.x;
    const int lane = tid & 31;
    const int wy   = tid >> 5;
    const int e0   = wy * 4;
    const int f0   = lane * 4;
    const long long ebase = (long long)blockIdx.x * TE;

    // dtype probe: int64 little-endian => high words (odd int32 slots) are 0.
    const int is64 = (ei32[1] == 0 && ei32[3] == 0 &&
                      ei32[5] == 0 && ei32[7] == 0) ? 1 : 0;

    // ---- gather z tiles ----
    #pragma unroll
    for (int q = 0; q < 4; q++) {
        const int e = e0 + q;
        long long ge  = ebase + e;
        long long gec = (ge < E) ? ge : (long long)(E - 1);
        const int sidx = load_idx(ei32, gec, is64, N);                 // src
        const int didx = load_idx(ei32, (long long)E + gec, is64, N);  // dst

        // z = [ h[dst] | h[src] | d_feat(20) | edge_attr(4) ]
        *(float4*)&Z[e * ZDIM + f0]       = *(const float4*)&h[(long long)didx * HID + f0];
        *(float4*)&Z[e * ZDIM + HID + f0] = *(const float4*)&h[(long long)sidx * HID + f0];

        if (lane == 0) {
            float rx = x[didx * 3 + 0] - x[sidx * 3 + 0];
            float ry = x[didx * 3 + 1] - x[sidx * 3 + 1];
            float rz = x[didx * 3 + 2] - x[sidx * 3 + 2];
            float d  = sqrtf(rx * rx + ry * ry + rz * rz + 1e-8f);
            sRel[e][0] = rx; sRel[e][1] = ry; sRel[e][2] = rz;
            sD[e] = d; sDst[e] = didx;
        }
        __syncwarp();
        float d = sD[e];
        if (lane < NG) {
            // GaussianSmearing: offset[g] = g*10/19, coeff = -0.5*(19/10)^2
            float t = d - (float)lane * (10.0f / 19.0f);
            Z[e * ZDIM + 2 * HID + lane] = __expf(-1.805f * t * t);
        } else if (lane < NG + EF) {
            Z[e * ZDIM + 2 * HID + NG + (lane - NG)] = eattr[gec * EF + (lane - NG)];
        }
    }
    __syncthreads();

    // ---- GEMM1: U = silu(Z @ We1 + be1) ----
    {
        float acc[4][4];
        gemm_core<ZDIM, ZDIM>(Z, We1, be1, acc, e0, f0);
        store_silu(acc, U, e0, f0);
    }
    __syncthreads();

    // ---- GEMM2: M = silu(U @ We2 + be2)  (M overwrites Z region) ----
    {
        float acc[4][4];
        gemm_core<HID, HID>(U, We2, be2, acc, e0, f0);
        store_silu(acc, M, e0, f0);
    }
    __syncthreads();

    // ---- eij = sigmoid(M @ Winf + binf) ----
    #pragma unroll
    for (int q = 0; q < 4; q++) {
        const int e = e0 + q;
        float p = 0.0f;
        #pragma unroll
        for (int r = 0; r < 4; r++) {
            int f = lane + 32 * r;
            p = fmaf(M[e * HID + f], Winf[f], p);
        }
        #pragma unroll
        for (int off = 16; off > 0; off >>= 1)
            p += __shfl_xor_sync(0xffffffffu, p, off);
        if (lane == 0)
            sE[e] = 1.0f / (1.0f + __expf(-(p + binf[0])));
    }

    // ---- GEMM3: V = silu(M @ Wx1 + bx1)  (V overwrites U region) ----
    {
        float acc[4][4];
        gemm_core<HID, HID>(M, Wx1, bx1, acc, e0, f0);
        store_silu(acc, V, e0, f0);
    }
    __syncthreads();

    // ---- xg = tanh(V @ Wx2) ----
    #pragma unroll
    for (int q = 0; q < 4; q++) {
        const int e = e0 + q;
        float p = 0.0f;
        #pragma unroll
        for (int r = 0; r < 4; r++) {
            int f = lane + 32 * r;
            p = fmaf(V[e * HID + f], Wx2[f], p);
        }
        #pragma unroll
        for (int off = 16; off > 0; off >>= 1)
            p += __shfl_xor_sync(0xffffffffu, p, off);
        if (lane == 0)
            sXg[e] = tanhf(p);
    }
    __syncthreads();

    // ---- scatter: mi[dst] += m*eij ; dx[dst] += rel/(d+1)*xg ----
    #pragma unroll
    for (int i = 0; i < 4; i++) {
        const int e = e0 + i;
        if (ebase + e < E) {
            const float eij = sE[e];
            float* mip = &g_mi[(long long)sDst[e] * HID + f0];
            #pragma unroll
            for (int j = 0; j < 4; j++)
                atomicAdd(mip + j, M[e * HID + f0 + j] * eij);
        }
    }
    if (lane < 12) {
        const int q = lane / 3, c = lane % 3;
        const int e = e0 + q;
        if (ebase + e < E) {
            float val = sRel[e][c] / (sD[e] + 1.0f) * sXg[e];
            atomicAdd(&g_dx[sDst[e] * 3 + c], val);
        }
    }
}

// ----------------------------------------------------------------------------
// Node kernel: h_out = h + (silu([mi,h]@Wn1+bn1) @ Wn2 + bn2);
//              x_out = x + dx * mask
// ----------------------------------------------------------------------------
__global__ void __launch_bounds__(NTHR, 2)
node_kernel(const float* __restrict__ h, const float* __restrict__ x,
            const float* __restrict__ mask,
            const float* __restrict__ Wn1, const float* __restrict__ bn1,
            const float* __restrict__ Wn2, const float* __restrict__ bn2,
            float* __restrict__ hout, float* __restrict__ xout, int N)
{
    extern __shared__ float smem[];
    float* NZ = smem;                  // [32][256]
    float* T  = smem + TE * NZDIM;     // [32][128]

    const int tid  = threadIdx.x;
    const int lane = tid & 31;
    const int wy   = tid >> 5;
    const int e0   = wy * 4;
    const int f0   = lane * 4;
    const long long nbase = (long long)blockIdx.x * TE;

    #pragma unroll
    for (int q = 0; q < 4; q++) {
        const int r = e0 + q;
        long long gn  = nbase + r;
        long long gnc = (gn < N) ? gn : (long long)(N - 1);
        *(float4*)&NZ[r * NZDIM + f0]       = *(const float4*)&g_mi[gnc * HID + f0];
        *(float4*)&NZ[r * NZDIM + HID + f0] = *(const float4*)&h[gnc * HID + f0];
    }
    __syncthreads();

    // T = silu(NZ @ Wn1 + bn1)
    {
        float acc[4][4];
        gemm_core<NZDIM, NZDIM>(NZ, Wn1, bn1, acc, e0, f0);
        store_silu(acc, T, e0, f0);
    }
    __syncthreads();

    // h_out = h + (T @ Wn2 + bn2)
    {
        float acc[4][4];
        gemm_core<HID, HID>(T, Wn2, bn2, acc, e0, f0);
        #pragma unroll
        for (int i = 0; i < 4; i++) {
            const int r = e0 + i;
            long long gn = nbase + r;
            if (gn < N) {
                float4 o;
                o.x = acc[i][0] + NZ[r * NZDIM + HID + f0 + 0];
                o.y = acc[i][1] + NZ[r * NZDIM + HID + f0 + 1];
                o.z = acc[i][2] + NZ[r * NZDIM + HID + f0 + 2];
                o.w = acc[i][3] + NZ[r * NZDIM + HID + f0 + 3];
                *(float4*)&hout[gn * HID + f0] = o;
            }
        }
    }

    // x_out = x + dx * mask
    if (lane < 12) {
        const int q = lane / 3, c = lane % 3;
        long long gn = nbase + e0 + q;
        if (gn < N)
            xout[gn * 3 + c] = x[gn * 3 + c] + g_dx[gn * 3 + c] * mask[gn];
    }
}

// ----------------------------------------------------------------------------
extern "C" void kernel_launch(void* const* d_in, const int* in_sizes, int n_in,
                              void* d_out, int out_size)
{
    const float* h     = (const float*)d_in[0];
    const float* x     = (const float*)d_in[1];
    const int*   ei32  = (const int*)d_in[2];     // int32 OR int64 (probed on device)
    const float* mask  = (const float*)d_in[3];
    const float* eattr = (const float*)d_in[4];
    const float* We1   = (const float*)d_in[5];
    const float* be1   = (const float*)d_in[6];
    const float* We2   = (const float*)d_in[7];
    const float* be2   = (const float*)d_in[8];
    const float* Winf  = (const float*)d_in[9];
    const float* binf  = (const float*)d_in[10];
    const float* Wx1   = (const float*)d_in[11];
    const float* bx1   = (const float*)d_in[12];
    const float* Wx2   = (const float*)d_in[13];
    const float* Wn1   = (const float*)d_in[14];
    const float* bn1   = (const float*)d_in[15];
    const float* Wn2   = (const float*)d_in[16];
    const float* bn2   = (const float*)d_in[17];

    const int N = in_sizes[0] / HID;
    const int E = in_sizes[2] / 2;   // element count (same for i32/i64)

    float* hout = (float*)d_out;
    float* xout = hout + (size_t)N * HID;

    const int edge_smem = (TE * ZDIM + TE * HID) * (int)sizeof(float);   // 52224 B
    const int node_smem = (TE * NZDIM + TE * HID) * (int)sizeof(float);  // 49152 B
    cudaFuncSetAttribute(edge_kernel, cudaFuncAttributeMaxDynamicSharedMemorySize, edge_smem);
    cudaFuncSetAttribute(node_kernel, cudaFuncAttributeMaxDynamicSharedMemorySize, node_smem);

    zero_kernel<<<(MAXN * HID + NTHR - 1) / NTHR, NTHR>>>();
    edge_kernel<<<(E + TE - 1) / TE, NTHR, edge_smem>>>(
        h, x, ei32, eattr, We1, be1, We2, be2, Winf, binf, Wx1, bx1, Wx2, E, N);
    node_kernel<<<(N + TE - 1) / TE, NTHR, node_smem>>>(
        h, x, mask, Wn1, bn1, Wn2, bn2, hout, xout, N);
}

// round 7
// speedup vs baseline: 1.1303x; 1.1303x over previous
#include <cuda_runtime.h>
#include <math.h>

#define HID   128
#define NG    20
#define EF    4
#define ZDIM  280      // 2*HID + NG + EF
#define NZDIM 256      // 2*HID
#define TE    32       // edges (or nodes) per CTA tile
#define NTHR  256
#define MAXN  50000

typedef unsigned long long u64;

// Scratch (static device arrays — no runtime allocation).
__device__ float g_mi[(size_t)MAXN * HID];
__device__ float g_dx[(size_t)MAXN * 3];

__device__ __forceinline__ float siluf(float v) {
    return v * (1.0f / (1.0f + __expf(-v)));
}

// ---- packed f32x2 helpers (sm_100+; SASS FFMA2 path ptxas won't emit) ----
__device__ __forceinline__ u64 pack2(float v) {           // splat
    u64 r; asm("mov.b64 %0, {%1, %1};" : "=l"(r) : "f"(v)); return r;
}
__device__ __forceinline__ void ffma2(u64& d, u64 a, u64 b) {
    asm("fma.rn.f32x2 %0, %1, %2, %0;" : "+l"(d) : "l"(a), "l"(b));
}
__device__ __forceinline__ void unpack2(u64 v, float& lo, float& hi) {
    asm("mov.b64 {%0, %1}, %2;" : "=f"(lo), "=f"(hi) : "l"(v));
}
// vector float4 reduction into global (no return) — 1 op instead of 4 atomics
__device__ __forceinline__ void red_add_v4(float* p, float a, float b, float c, float d) {
    asm volatile("red.global.add.v4.f32 [%0], {%1, %2, %3, %4};"
                 :: "l"(p), "f"(a), "f"(b), "f"(c), "f"(d) : "memory");
}

// Robust edge-index fetch: buffer may be int32 or little-endian int64.
__device__ __forceinline__ int load_idx(const int* __restrict__ ei32,
                                        long long pos, int is64, int N) {
    int v = is64 ? ei32[2 * pos] : ei32[pos];
    v = v < 0 ? 0 : v;
    return v >= N ? N - 1 : v;
}

// ----------------------------------------------------------------------------
// Packed-f32x2 tile GEMM: C[32][128] = A[32][K] @ W[K][128] + bias
// lane -> 4 consecutive output features (2 packed pairs), warp -> 4 rows.
// W rows load as ulonglong2 (naturally paired along j); A scalars splat once
// per (row, k) and feed 2 FFMA2. Exact fp32 math at 2x FFMA throughput.
// ----------------------------------------------------------------------------
template<int K, int AS>
__device__ __forceinline__ void gemm2_core(const float* __restrict__ sA,
                                           const float* __restrict__ W,
                                           const float* __restrict__ bias,
                                           u64 (&acc)[4][2], int e0, int f0)
{
    ulonglong2 bv = *(const ulonglong2*)&bias[f0];
    #pragma unroll
    for (int i = 0; i < 4; i++) { acc[i][0] = bv.x; acc[i][1] = bv.y; }

    #pragma unroll 2
    for (int k = 0; k < K; k += 4) {
        ulonglong2 wq[4];
        #pragma unroll
        for (int kk = 0; kk < 4; kk++)
            wq[kk] = *(const ulonglong2*)&W[(k + kk) * HID + f0];
        #pragma unroll
        for (int i = 0; i < 4; i++) {
            float4 aq = *(const float4*)&sA[(e0 + i) * AS + k];  // smem broadcast
            u64 a0 = pack2(aq.x), a1 = pack2(aq.y), a2 = pack2(aq.z), a3 = pack2(aq.w);
            ffma2(acc[i][0], a0, wq[0].x);  ffma2(acc[i][1], a0, wq[0].y);
            ffma2(acc[i][0], a1, wq[1].x);  ffma2(acc[i][1], a1, wq[1].y);
            ffma2(acc[i][0], a2, wq[2].x);  ffma2(acc[i][1], a2, wq[2].y);
            ffma2(acc[i][0], a3, wq[3].x);  ffma2(acc[i][1], a3, wq[3].y);
        }
    }
}

__device__ __forceinline__ void store_silu2(u64 (&acc)[4][2],
                                            float* __restrict__ sC, int e0, int f0)
{
    #pragma unroll
    for (int i = 0; i < 4; i++) {
        float4 o;
        unpack2(acc[i][0], o.x, o.y);
        unpack2(acc[i][1], o.z, o.w);
        o.x = siluf(o.x); o.y = siluf(o.y); o.z = siluf(o.z); o.w = siluf(o.w);
        *(float4*)&sC[(e0 + i) * HID + f0] = o;
    }
}

// ----------------------------------------------------------------------------
__global__ void zero_kernel()
{
    int i = blockIdx.x * blockDim.x + threadIdx.x;
    if (i < MAXN * HID / 4) ((float4*)g_mi)[i] = make_float4(0.f, 0.f, 0.f, 0.f);
    if (i < MAXN * 3)       g_dx[i] = 0.0f;
}

// ----------------------------------------------------------------------------
// Edge kernel: fused z -> silu -> silu -> {eij, silu -> xg} -> scatter.
// ----------------------------------------------------------------------------
__global__ void __launch_bounds__(NTHR, 2)
edge_kernel(const float* __restrict__ h, const float* __restrict__ x,
            const int* __restrict__ ei32, const float* __restrict__ eattr,
            const float* __restrict__ We1, const float* __restrict__ be1,
            const float* __restrict__ We2, const float* __restrict__ be2,
            const float* __restrict__ Winf, const float* __restrict__ binf,
            const float* __restrict__ Wx1, const float* __restrict__ bx1,
            const float* __restrict__ Wx2, int E, int N)
{
    extern __shared__ float smem[];
    float* Z = smem;                 // [TE][ZDIM]
    float* U = smem + TE * ZDIM;     // [TE][HID]
    float* M = smem;                 // alias Z (dead after GEMM1)
    float* V = U;                    // alias U (dead after GEMM2)

    __shared__ float sRel[TE][3];
    __shared__ float sD[TE];
    __shared__ float sE[TE];
    __shared__ float sXg[TE];
    __shared__ int   sDst[TE];

    const int tid  = threadIdx.x;
    const int lane = tid & 31;
    const int wy   = tid >> 5;
    const int e0   = wy * 4;
    const int f0   = lane * 4;
    const long long ebase = (long long)blockIdx.x * TE;

    // dtype probe: int64 little-endian => odd int32 slots are 0.
    const int is64 = (ei32[1] == 0 && ei32[3] == 0 &&
                      ei32[5] == 0 && ei32[7] == 0) ? 1 : 0;

    // ---- gather z tiles ----
    #pragma unroll
    for (int q = 0; q < 4; q++) {
        const int e = e0 + q;
        long long ge  = ebase + e;
        long long gec = (ge < E) ? ge : (long long)(E - 1);
        const int sidx = load_idx(ei32, gec, is64, N);                 // src
        const int didx = load_idx(ei32, (long long)E + gec, is64, N);  // dst

        *(float4*)&Z[e * ZDIM + f0]       = *(const float4*)&h[(long long)didx * HID + f0];
        *(float4*)&Z[e * ZDIM + HID + f0] = *(const float4*)&h[(long long)sidx * HID + f0];

        if (lane == 0) {
            float rx = x[didx * 3 + 0] - x[sidx * 3 + 0];
            float ry = x[didx * 3 + 1] - x[sidx * 3 + 1];
            float rz = x[didx * 3 + 2] - x[sidx * 3 + 2];
            float d  = sqrtf(rx * rx + ry * ry + rz * rz + 1e-8f);
            sRel[e][0] = rx; sRel[e][1] = ry; sRel[e][2] = rz;
            sD[e] = d; sDst[e] = didx;
        }
        __syncwarp();
        float d = sD[e];
        if (lane < NG) {
            float t = d - (float)lane * (10.0f / 19.0f);
            Z[e * ZDIM + 2 * HID + lane] = __expf(-1.805f * t * t);
        } else if (lane < NG + EF) {
            Z[e * ZDIM + 2 * HID + NG + (lane - NG)] = eattr[gec * EF + (lane - NG)];
        }
    }
    __syncthreads();

    // ---- GEMM1: U = silu(Z @ We1 + be1) ----
    {
        u64 acc[4][2];
        gemm2_core<ZDIM, ZDIM>(Z, We1, be1, acc, e0, f0);
        store_silu2(acc, U, e0, f0);
    }
    __syncthreads();

    // ---- GEMM2: M = silu(U @ We2 + be2)  (M overwrites Z region) ----
    {
        u64 acc[4][2];
        gemm2_core<HID, HID>(U, We2, be2, acc, e0, f0);
        store_silu2(acc, M, e0, f0);
    }
    __syncthreads();

    // ---- eij = sigmoid(M @ Winf + binf) ----
    #pragma unroll
    for (int q = 0; q < 4; q++) {
        const int e = e0 + q;
        float p = 0.0f;
        #pragma unroll
        for (int r = 0; r < 4; r++) {
            int f = lane + 32 * r;
            p = fmaf(M[e * HID + f], Winf[f], p);
        }
        #pragma unroll
        for (int off = 16; off > 0; off >>= 1)
            p += __shfl_xor_sync(0xffffffffu, p, off);
        if (lane == 0)
            sE[e] = 1.0f / (1.0f + __expf(-(p + binf[0])));
    }

    // ---- GEMM3: V = silu(M @ Wx1 + bx1)  (V overwrites U region) ----
    {
        u64 acc[4][2];
        gemm2_core<HID, HID>(M, Wx1, bx1, acc, e0, f0);
        store_silu2(acc, V, e0, f0);
    }
    __syncthreads();

    // ---- xg = tanh(V @ Wx2) ----
    #pragma unroll
    for (int q = 0; q < 4; q++) {
        const int e = e0 + q;
        float p = 0.0f;
        #pragma unroll
        for (int r = 0; r < 4; r++) {
            int f = lane + 32 * r;
            p = fmaf(V[e * HID + f], Wx2[f], p);
        }
        #pragma unroll
        for (int off = 16; off > 0; off >>= 1)
            p += __shfl_xor_sync(0xffffffffu, p, off);
        if (lane == 0)
            sXg[e] = tanhf(p);
    }
    __syncthreads();

    // ---- scatter: mi[dst] += m*eij (vector red) ; dx[dst] += rel/(d+1)*xg ----
    #pragma unroll
    for (int i = 0; i < 4; i++) {
        const int e = e0 + i;
        if (ebase + e < E) {
            const float eij = sE[e];
            float* mip = &g_mi[(long long)sDst[e] * HID + f0];
            red_add_v4(mip,
                       M[e * HID + f0 + 0] * eij, M[e * HID + f0 + 1] * eij,
                       M[e * HID + f0 + 2] * eij, M[e * HID + f0 + 3] * eij);
        }
    }
    if (lane < 12) {
        const int q = lane / 3, c = lane % 3;
        const int e = e0 + q;
        if (ebase + e < E) {
            float val = sRel[e][c] / (sD[e] + 1.0f) * sXg[e];
            atomicAdd(&g_dx[sDst[e] * 3 + c], val);
        }
    }
}

// ----------------------------------------------------------------------------
// Node kernel: h_out = h + (silu([mi,h]@Wn1+bn1) @ Wn2 + bn2);
//              x_out = x + dx * mask
// ----------------------------------------------------------------------------
__global__ void __launch_bounds__(NTHR, 2)
node_kernel(const float* __restrict__ h, const float* __restrict__ x,
            const float* __restrict__ mask,
            const float* __restrict__ Wn1, const float* __restrict__ bn1,
            const float* __restrict__ Wn2, const float* __restrict__ bn2,
            float* __restrict__ hout, float* __restrict__ xout, int N)
{
    extern __shared__ float smem[];
    float* NZ = smem;                  // [32][256]
    float* T  = smem + TE * NZDIM;     // [32][128]

    const int tid  = threadIdx.x;
    const int lane = tid & 31;
    const int wy   = tid >> 5;
    const int e0   = wy * 4;
    const int f0   = lane * 4;
    const long long nbase = (long long)blockIdx.x * TE;

    #pragma unroll
    for (int q = 0; q < 4; q++) {
        const int r = e0 + q;
        long long gn  = nbase + r;
        long long gnc = (gn < N) ? gn : (long long)(N - 1);
        *(float4*)&NZ[r * NZDIM + f0]       = *(const float4*)&g_mi[gnc * HID + f0];
        *(float4*)&NZ[r * NZDIM + HID + f0] = *(const float4*)&h[gnc * HID + f0];
    }
    __syncthreads();

    // T = silu(NZ @ Wn1 + bn1)
    {
        u64 acc[4][2];
        gemm2_core<NZDIM, NZDIM>(NZ, Wn1, bn1, acc, e0, f0);
        store_silu2(acc, T, e0, f0);
    }
    __syncthreads();

    // h_out = h + (T @ Wn2 + bn2)
    {
        u64 acc[4][2];
        gemm2_core<HID, HID>(T, Wn2, bn2, acc, e0, f0);
        #pragma unroll
        for (int i = 0; i < 4; i++) {
            const int r = e0 + i;
            long long gn = nbase + r;
            if (gn < N) {
                float4 o;
                unpack2(acc[i][0], o.x, o.y);
                unpack2(acc[i][1], o.z, o.w);
                o.x += NZ[r * NZDIM + HID + f0 + 0];
                o.y += NZ[r * NZDIM + HID + f0 + 1];
                o.z += NZ[r * NZDIM + HID + f0 + 2];
                o.w += NZ[r * NZDIM + HID + f0 + 3];
                *(float4*)&hout[gn * HID + f0] = o;
            }
        }
    }

    // x_out = x + dx * mask
    if (lane < 12) {
        const int q = lane / 3, c = lane % 3;
        long long gn = nbase + e0 + q;
        if (gn < N)
            xout[gn * 3 + c] = x[gn * 3 + c] + g_dx[gn * 3 + c] * mask[gn];
    }
}

// ----------------------------------------------------------------------------
extern "C" void kernel_launch(void* const* d_in, const int* in_sizes, int n_in,
                              void* d_out, int out_size)
{
    const float* h     = (const float*)d_in[0];
    const float* x     = (const float*)d_in[1];
    const int*   ei32  = (const int*)d_in[2];     // int32 OR int64 (device-probed)
    const float* mask  = (const float*)d_in[3];
    const float* eattr = (const float*)d_in[4];
    const float* We1   = (const float*)d_in[5];
    const float* be1   = (const float*)d_in[6];
    const float* We2   = (const float*)d_in[7];
    const float* be2   = (const float*)d_in[8];
    const float* Winf  = (const float*)d_in[9];
    const float* binf  = (const float*)d_in[10];
    const float* Wx1   = (const float*)d_in[11];
    const float* bx1   = (const float*)d_in[12];
    const float* Wx2   = (const float*)d_in[13];
    const float* Wn1   = (const float*)d_in[14];
    const float* bn1   = (const float*)d_in[15];
    const float* Wn2   = (const float*)d_in[16];
    const float* bn2   = (const float*)d_in[17];

    const int N = in_sizes[0] / HID;
    const int E = in_sizes[2] / 2;

    float* hout = (float*)d_out;
    float* xout = hout + (size_t)N * HID;

    const int edge_smem = (TE * ZDIM + TE * HID) * (int)sizeof(float);   // 52224 B
    const int node_smem = (TE * NZDIM + TE * HID) * (int)sizeof(float);  // 49152 B
    cudaFuncSetAttribute(edge_kernel, cudaFuncAttributeMaxDynamicSharedMemorySize, edge_smem);
    cudaFuncSetAttribute(node_kernel, cudaFuncAttributeMaxDynamicSharedMemorySize, node_smem);

    zero_kernel<<<(MAXN * HID + NTHR - 1) / NTHR, NTHR>>>();
    edge_kernel<<<(E + TE - 1) / TE, NTHR, edge_smem>>>(
        h, x, ei32, eattr, We1, be1, We2, be2, Winf, binf, Wx1, bx1, Wx2, E, N);
    node_kernel<<<(N + TE - 1) / TE, NTHR, node_smem>>>(
        h, x, mask, Wn1, bn1, Wn2, bn2, hout, xout, N);
}